// round 11
// baseline (speedup 1.0000x reference)
#include <cuda_runtime.h>
#include <math.h>

#define N_DIM    64
#define B_ROWS   1024
#define QCH      32
#define NGRP     32                // knn row-groups of 32
#define NQ       8                 // j-eighths (128 js each)
#define NBLK_KNN (NGRP * NQ)       // 256
#define NBLK_KDE (N_DIM * 16)     // 1024
#define NBLK_B   (NBLK_KNN + NBLK_KDE)  // 1280
#define TS       3.5f              // truncation radius, h-units
#define K2C      (-0.72134752f)    // -0.5*log2(e)
#define NMOM     13                // Hermite terms 0..12

// Scratch (device globals — no allocation allowed)
__device__ float g_logrho[B_ROWS];
__device__ float g_cols[N_DIM * B_ROWS];   // sorted columns, scaled by 1/h
__device__ float g_invh[N_DIM];
__device__ float g_partials[N_DIM * QCH];
__device__ float g_t6[NGRP][NQ][32][6];
__device__ int   g_qc[NGRP];               // self-resetting quarter counters
__device__ int   g_done;                   // reset by last block each run

__device__ __forceinline__ float ex2(float x) {
    float r;
    asm("ex2.approx.ftz.f32 %0, %1;" : "=f"(r) : "f"(x));
    return r;
}

// ---------------------------------------------------------------------------
// Kernel A: prep only — column std -> h, scale by 1/h, bitonic sort.
// grid = 64, block = 256.
// ---------------------------------------------------------------------------
__global__ __launch_bounds__(256)
void kprep(const float* __restrict__ act) {
    __shared__ float u[B_ROWS];
    __shared__ float red[256];
    __shared__ float sscale;

    const int tid = threadIdx.x;
    const int col = blockIdx.x;

    float s1 = 0.f, s2 = 0.f;
    #pragma unroll
    for (int t = 0; t < 4; t++) {
        float v = act[(tid + 256 * t) * N_DIM + col];
        u[tid + 256 * t] = v;
        s1 += v;
        s2 += v * v;
    }
    red[tid] = s1; __syncthreads();
    for (int st = 128; st > 0; st >>= 1) {
        if (tid < st) red[tid] += red[tid + st];
        __syncthreads();
    }
    float tot1 = red[0]; __syncthreads();
    red[tid] = s2; __syncthreads();
    for (int st = 128; st > 0; st >>= 1) {
        if (tid < st) red[tid] += red[tid + st];
        __syncthreads();
    }
    if (tid == 0) {
        const float Bf = (float)B_ROWS;
        float mean = tot1 / Bf;
        float var  = (red[0] - Bf * mean * mean) / (Bf - 1.0f);
        float stdv = sqrtf(fmaxf(var, 0.f));
        float h    = fmaxf(1.06f * stdv * 0.25f, 1e-4f);  // 1024^-0.2 = 0.25
        float ih   = 1.0f / h;
        g_invh[col] = ih;
        sscale = ih;
    }
    __syncthreads();
    const float sc = sscale;
    #pragma unroll
    for (int t = 0; t < 4; t++)
        u[tid + 256 * t] *= sc;

    for (int kk2 = 2; kk2 <= B_ROWS; kk2 <<= 1) {
        for (int jj = kk2 >> 1; jj > 0; jj >>= 1) {
            __syncthreads();
            #pragma unroll
            for (int t = 0; t < 4; t++) {
                int i = tid + 256 * t;
                int ixj = i ^ jj;
                if (ixj > i) {
                    bool up = ((i & kk2) == 0);
                    float a = u[i], b = u[ixj];
                    if ((a > b) == up) { u[i] = b; u[ixj] = a; }
                }
            }
        }
    }
    __syncthreads();
    #pragma unroll
    for (int t = 0; t < 4; t++)
        g_cols[col * B_ROWS + tid + 256 * t] = u[tid + 256 * t];
}

// ---------------------------------------------------------------------------
// Kernel B: knn (blocks 0..255) + kde (blocks 256..1279) + final assembly.
// 256 threads. knn: 32 rows (4/warp), 128 js in two 64-j subtiles.
// ---------------------------------------------------------------------------
struct KnnS {
    float tile[64][68];    // stride 68: conflict-free LDS.128
    float xq[32][64];
    float jn[64];
    float qn[32];
};
struct KdeS {
    float u[B_ROWS];
    float refl[2][32][5];
    float mom[2][4][NMOM];
    int   bnd[2][4];
    double dred[256];
};
union SmemU { KnnS knn; KdeS kde; };

__global__ __launch_bounds__(256)
void kB(const float* __restrict__ act, const int* __restrict__ kp,
        float* __restrict__ out) {
    __shared__ __align__(16) SmemU S;
    __shared__ int s_flag;

    const int tid  = threadIdx.x;
    const int bx   = blockIdx.x;
    const int lane = tid & 31;
    const int w    = tid >> 5;

    if (bx < NBLK_KNN) {
        // ================= KNN ============================================
        KnnS* K = &S.knn;
        const int g = bx >> 3, q = bx & 7;
        const int row0 = g * 32, jbase = q * 128;

        // 32 query rows + norms (16-lane shuffle reduce: 16 float4 per row)
        {
            const float4* qsrc = (const float4*)(act + row0 * N_DIM);
            #pragma unroll
            for (int t = 0; t < 2; t++) {
                int fi = tid + t * 256;
                float4 v = qsrc[fi];
                ((float4*)K->xq)[fi] = v;
                float s = v.x * v.x + v.y * v.y + v.z * v.z + v.w * v.w;
                s += __shfl_down_sync(0xffffffffu, s, 8, 16);
                s += __shfl_down_sync(0xffffffffu, s, 4, 16);
                s += __shfl_down_sync(0xffffffffu, s, 2, 16);
                s += __shfl_down_sync(0xffffffffu, s, 1, 16);
                if ((lane & 15) == 0) K->qn[fi >> 4] = s;
            }
        }

        float m[4][6];
        #pragma unroll
        for (int r = 0; r < 4; r++)
            #pragma unroll
            for (int i = 0; i < 6; i++) m[r][i] = 3.4e38f;

        for (int sub = 0; sub < 2; sub++) {
            __syncthreads();
            // 64-row tile + fused norms
            const float4* gsrc = (const float4*)(act + (jbase + sub * 64) * N_DIM);
            #pragma unroll
            for (int it = 0; it < 4; it++) {
                int fi = tid + it * 256;
                float4 v = gsrc[fi];
                *(float4*)&K->tile[fi >> 4][(fi & 15) * 4] = v;
                float s = v.x * v.x + v.y * v.y + v.z * v.z + v.w * v.w;
                s += __shfl_down_sync(0xffffffffu, s, 8, 16);
                s += __shfl_down_sync(0xffffffffu, s, 4, 16);
                s += __shfl_down_sync(0xffffffffu, s, 2, 16);
                s += __shfl_down_sync(0xffffffffu, s, 1, 16);
                if ((lane & 15) == 0) K->jn[fi >> 4] = s;
            }
            __syncthreads();

            float acc[4][2];
            #pragma unroll
            for (int r = 0; r < 4; r++) { acc[r][0] = 0.f; acc[r][1] = 0.f; }

            #pragma unroll
            for (int c = 0; c < 16; c++) {          // 4-dim chunks
                float4 qr[4];
                #pragma unroll
                for (int r = 0; r < 4; r++)
                    qr[r] = *(const float4*)&K->xq[4 * w + r][c * 4];
                #pragma unroll
                for (int s = 0; s < 2; s++) {
                    const float4 b = *(const float4*)&K->tile[lane + 32 * s][c * 4];
                    #pragma unroll
                    for (int r = 0; r < 4; r++) {
                        float a = acc[r][s];
                        a = fmaf(qr[r].x, b.x, a);
                        a = fmaf(qr[r].y, b.y, a);
                        a = fmaf(qr[r].z, b.z, a);
                        a = fmaf(qr[r].w, b.w, a);
                        acc[r][s] = a;
                    }
                }
            }
            #pragma unroll
            for (int s = 0; s < 2; s++) {
                const float nj = K->jn[lane + 32 * s];
                #pragma unroll
                for (int r = 0; r < 4; r++) {
                    float v = fmaf(acc[r][s], -2.f, nj);
                    if (v < m[r][5]) {
                        m[r][5] = v;
                        #pragma unroll
                        for (int i = 5; i > 0; i--)
                            if (m[r][i] < m[r][i - 1]) {
                                float tm = m[r][i]; m[r][i] = m[r][i - 1]; m[r][i - 1] = tm;
                            }
                    }
                }
            }
        }

        // per-row extract sorted top-6 over lanes, add qn, store
        #pragma unroll
        for (int r = 0; r < 4; r++) {
            float l0 = m[r][0], l1 = m[r][1], l2 = m[r][2];
            float l3 = m[r][3], l4 = m[r][4], l5 = m[r][5];
            float keep = 3.4e38f;
            #pragma unroll
            for (int i = 0; i < 6; i++) {
                float mv = l0;
                #pragma unroll
                for (int off = 16; off; off >>= 1)
                    mv = fminf(mv, __shfl_xor_sync(0xffffffffu, mv, off));
                if (lane == i) keep = mv;
                unsigned msk = __ballot_sync(0xffffffffu, l0 == mv);
                if (lane == (__ffs(msk) - 1)) {
                    l0 = l1; l1 = l2; l2 = l3; l3 = l4; l4 = l5; l5 = 3.4e38f;
                }
            }
            if (lane < 6)
                g_t6[g][q][4 * w + r][lane] = keep + K->qn[4 * w + r];
        }
        __syncthreads();
        if (tid == 0) {
            __threadfence();
            int old = atomicAdd(&g_qc[g], 1);
            s_flag = (old == NQ - 1);
        }
        __syncthreads();
        if (s_flag) {
            __threadfence();
            if (tid < 32) {
                int kk = *kp; if (kk > 5) kk = 5;
                float best[6];
                #pragma unroll
                for (int i = 0; i < 6; i++) best[i] = 3.4e38f;
                #pragma unroll
                for (int qq = 0; qq < NQ; qq++) {
                    #pragma unroll
                    for (int i = 0; i < 6; i++) {
                        float v = g_t6[g][qq][tid][i];
                        if (v < best[5]) {
                            best[5] = v;
                            #pragma unroll
                            for (int j2 = 5; j2 > 0; j2--)
                                if (best[j2] < best[j2 - 1]) {
                                    float tm = best[j2]; best[j2] = best[j2 - 1]; best[j2 - 1] = tm;
                                }
                        }
                    }
                }
                g_logrho[row0 + tid] = logf(fmaxf(best[kk], 1e-12f));
            }
            if (tid == 0) g_qc[g] = 0;   // reset for graph replay
        }
    } else {
        // ================= KDE (Hermite moments, float4 body) =============
        KdeS* D = &S.kde;
        const int idx  = bx - NBLK_KNN;
        const int col  = idx >> 4;
        const int cp   = idx & 15;
        const int half = w >> 2;
        const int wl   = w & 3;
        const int chunk = half ? (31 - cp) : cp;

        ((float4*)D->u)[tid] = ((const float4*)(g_cols + col * B_ROWS))[tid];
        __syncthreads();

        const float ih = g_invh[col];
        const int   q0 = chunk * 32;
        const float x  = D->u[q0 + lane];
        const float c2 = 2.0f * ih;
        const float cen = 0.5f * (D->u[q0] + D->u[q0 + 31]);

        if (tid < 8) {
            int h2 = tid >> 2, i2 = tid & 3;
            int ch = h2 ? (31 - cp) : cp;
            float xmn = D->u[ch * 32], xmx = D->u[ch * 32 + 31];
            float tgt = (i2 == 0) ? xmn - TS : (i2 == 1) ? xmx + TS
                      : (i2 == 2) ? TS - xmn : c2 - TS - xmx;
            int pos = 0;
            #pragma unroll
            for (int step = 1024; step; step >>= 1) {
                int np = pos + step;
                if (np <= B_ROWS && D->u[np - 1] < tgt) pos = np;
            }
            D->bnd[h2][i2] = pos;
        }
        __syncthreads();
        const int a0 = D->bnd[half][0], b0 = D->bnd[half][1];
        const int bL = D->bnd[half][2], aR = D->bnd[half][3];

        // Hermite moments, float4 vectorized (4 independent chains)
        {
            constexpr float INV[NMOM] = {0.f, 1.f, 0.5f, 0.33333334f, 0.25f,
                0.2f, 0.16666667f, 0.14285715f, 0.125f, 0.11111111f, 0.1f,
                0.09090909f, 0.08333334f};
            float M[NMOM];
            #pragma unroll
            for (int n = 0; n < NMOM; n++) M[n] = 0.f;
            const int t128 = wl * 32 + lane;

            #define HSTEP(val) do {                                   \
                float uj_ = (val) - cen;                              \
                float wg_ = ex2(K2C * uj_ * uj_);                     \
                float bp_ = wg_, bc_ = wg_ * uj_;                     \
                M[0] += bp_; M[1] += bc_;                             \
                _Pragma("unroll")                                     \
                for (int n_ = 1; n_ < NMOM - 1; n_++) {               \
                    float bn_ = fmaf(uj_, bc_, -bp_) * INV[n_ + 1];   \
                    M[n_ + 1] += bn_; bp_ = bc_; bc_ = bn_;           \
                }                                                     \
            } while (0)

            int a0v = (a0 + 3) & ~3;
            if (a0v > b0) a0v = b0;
            int b0v = b0 & ~3;
            if (b0v < a0v) b0v = a0v;
            for (int j = a0 + t128; j < a0v; j += 128) HSTEP(D->u[j]);
            for (int j = b0v + t128; j < b0; j += 128) HSTEP(D->u[j]);
            for (int j = a0v + 4 * t128; j < b0v; j += 512) {
                float4 y = *(const float4*)(D->u + j);
                HSTEP(y.x); HSTEP(y.y); HSTEP(y.z); HSTEP(y.w);
            }
            #undef HSTEP

            #pragma unroll
            for (int n = 0; n < NMOM; n++) {
                #pragma unroll
                for (int off = 16; off; off >>= 1)
                    M[n] += __shfl_xor_sync(0xffffffffu, M[n], off);
            }
            if (lane == 0) {
                #pragma unroll
                for (int n = 0; n < NMOM; n++) D->mom[half][wl][n] = M[n];
            }
        }

        // reflections: direct, contiguous per-warp slices
        {
            float A0 = 0.f, A1 = 0.f;
            int l0 = (bL * wl) >> 2, l1 = (bL * (wl + 1)) >> 2;
            for (int j = l0; j < l1; j++) {
                float s = x + D->u[j];
                A1 += ex2(K2C * s * s);
            }
            const int rlen = B_ROWS - aR;
            const float xc = x - c2;
            int r0 = aR + ((rlen * wl) >> 2), r1 = aR + ((rlen * (wl + 1)) >> 2);
            for (int j = r0; j < r1; j++) {
                float s = xc + D->u[j];
                A0 += ex2(K2C * s * s);
            }
            D->refl[half][lane][wl] = A0 + A1;
        }
        __syncthreads();

        if (wl == 0) {
            float Mn[NMOM];
            #pragma unroll
            for (int n = 0; n < NMOM; n++)
                Mn[n] = (D->mom[half][0][n] + D->mom[half][1][n])
                      + (D->mom[half][2][n] + D->mom[half][3][n]);
            const float delta = x - cen;
            float f = Mn[NMOM - 1];
            #pragma unroll
            for (int n = NMOM - 2; n >= 0; n--)
                f = fmaf(f, delta, Mn[n]);
            f += (D->refl[half][lane][0] + D->refl[half][lane][1])
               + (D->refl[half][lane][2] + D->refl[half][lane][3]);

            const float Bf = (float)B_ROWS;
            const float scale = ih * (1.0f / (Bf * 2.5066282746310002f));
            float l = logf(f * scale + 1e-8f);
            #pragma unroll
            for (int off = 16; off; off >>= 1)
                l += __shfl_xor_sync(0xffffffffu, l, off);
            if (lane == 0)
                g_partials[col * QCH + chunk] = l;
        }
    }

    // ================= common completion + final assembly =================
    __syncthreads();
    if (tid == 0) {
        __threadfence();
        unsigned p = atomicAdd(&g_done, 1);
        s_flag = (p == NBLK_B - 1);
    }
    __syncthreads();
    if (!s_flag) return;
    __threadfence();

    if (tid < N_DIM) {
        float t = 0.f;
        #pragma unroll
        for (int c = 0; c < QCH; c++)
            t += g_partials[tid * QCH + c];
        out[1 + tid] = -t / (float)B_ROWS;
    }
    {
        double* dred = S.kde.dred;
        double s = 0.0;
        for (int i = tid; i < B_ROWS; i += 256) s += (double)g_logrho[i];
        dred[tid] = s; __syncthreads();
        for (int st = 128; st > 0; st >>= 1) {
            if (tid < st) dred[tid] += dred[tid + st];
            __syncthreads();
        }
        if (tid == 0) {
            const int k = *kp;
            const double EULER    = 0.5772156649015328606;
            const double DG_B     = 6.9309834448765934;     // psi(1024)
            const double LGAMMA33 = 81.55795945611503558;   // lgamma(64/2+1)
            const double LOG_PI   = 1.1447298858494001741;
            const double INV_LN2  = 1.4426950408889634074;
            double dg_k = -EULER;
            for (int i = 1; i < k; i++) dg_k += 1.0 / (double)i;
            double log_c_d = 0.5 * (double)N_DIM * LOG_PI - LGAMMA33;
            double mean_lr = dred[0] / (double)B_ROWS;
            double h_nats = -dg_k + DG_B + log_c_d + (double)N_DIM * 0.5 * mean_lr;
            out[0] = (float)(h_nats * INV_LN2);
            g_done = 0;   // reset for graph replay
        }
    }
}

// ---------------------------------------------------------------------------
extern "C" void kernel_launch(void* const* d_in, const int* in_sizes, int n_in,
                              void* d_out, int out_size) {
    const float* act = (const float*)d_in[0];
    const int*   kp  = (const int*)d_in[1];
    float* out = (float*)d_out;
    (void)in_sizes; (void)n_in; (void)out_size;

    kprep<<<N_DIM, 256>>>(act);
    kB<<<NBLK_B, 256>>>(act, kp, out);
}

// round 12
// speedup vs baseline: 1.1450x; 1.1450x over previous
#include <cuda_runtime.h>
#include <math.h>

#define N_DIM    64
#define B_ROWS   1024
#define QCH      32
#define NGRP     32                // knn row-groups of 32
#define NQ       4                 // j-quarters (256 js each)
#define NBLK_KNN (NGRP * NQ)       // 128
#define NBLK_K2  256               // 64 cols x 4 (8 chunks per block)
#define TS       3.5f              // truncation radius, h-units
#define K2C      (-0.72134752f)    // -0.5*log2(e)
#define NMOM     13                // Hermite terms 0..12

// Scratch (device globals — no allocation allowed)
__device__ float g_logrho[B_ROWS];
__device__ float g_cols[N_DIM * B_ROWS];   // sorted columns, scaled by 1/h
__device__ float g_invh[N_DIM];
__device__ float g_partials[N_DIM * QCH];
__device__ float g_t6[NGRP][NQ][32][6];
__device__ int   g_qc[NGRP];               // self-resetting quarter counters
__device__ int   g_done;                   // reset by k1 block 0 each run

__device__ __forceinline__ float ex2(float x) {
    float r;
    asm("ex2.approx.ftz.f32 %0, %1;" : "=f"(r) : "f"(x));
    return r;
}

// ---------------------------------------------------------------------------
// Kernel 1: knn (blocks 0..127) + prep (blocks 128..191), 256 threads.
// knn block: 32 rows (4/warp), 256 js (2 tiles of 128); fused shuffle norms.
// ---------------------------------------------------------------------------
struct KnnS {
    float tile[128][68];   // stride 68: conflict-free LDS.128
    float xq[32][64];
    float jn[128];
    float qn[32];
    int   merge;
};
struct PrepS {
    float u[B_ROWS];
    float red[256];
    float scale;
};

__global__ __launch_bounds__(256)
void k1(const float* __restrict__ act, const int* __restrict__ kp) {
    __shared__ __align__(16) char sm[sizeof(KnnS) > sizeof(PrepS) ? sizeof(KnnS) : sizeof(PrepS)];
    const int tid = threadIdx.x;
    const int bx  = blockIdx.x;

    if (bx == 0 && tid == 0) g_done = 0;

    if (bx < NBLK_KNN) {
        KnnS* S = (KnnS*)sm;
        const int g = bx >> 2, q = bx & 3;
        const int row0 = g * 32, jbase = q * 256;
        const int lane = tid & 31, w = tid >> 5;

        // 32 query rows + norms (half-warp shuffle reduce)
        {
            const float4* qsrc = (const float4*)(act + row0 * N_DIM);
            #pragma unroll
            for (int t = 0; t < 2; t++) {
                int fi = tid + t * 256;
                float4 v = qsrc[fi];
                ((float4*)S->xq)[fi] = v;
                float s = v.x * v.x + v.y * v.y + v.z * v.z + v.w * v.w;
                s += __shfl_down_sync(0xffffffffu, s, 8, 16);
                s += __shfl_down_sync(0xffffffffu, s, 4, 16);
                s += __shfl_down_sync(0xffffffffu, s, 2, 16);
                s += __shfl_down_sync(0xffffffffu, s, 1, 16);
                if ((lane & 15) == 0) S->qn[fi >> 4] = s;
            }
        }

        float m[4][6];
        #pragma unroll
        for (int r = 0; r < 4; r++)
            #pragma unroll
            for (int i = 0; i < 6; i++) m[r][i] = 3.4e38f;

        for (int t = 0; t < 2; t++) {
            __syncthreads();
            // 128-row tile + fused norms
            const float4* gsrc = (const float4*)(act + (jbase + t * 128) * N_DIM);
            #pragma unroll
            for (int it = 0; it < 8; it++) {
                int fi = tid + it * 256;
                float4 v = gsrc[fi];
                *(float4*)&S->tile[fi >> 4][(fi & 15) * 4] = v;
                float s = v.x * v.x + v.y * v.y + v.z * v.z + v.w * v.w;
                s += __shfl_down_sync(0xffffffffu, s, 8, 16);
                s += __shfl_down_sync(0xffffffffu, s, 4, 16);
                s += __shfl_down_sync(0xffffffffu, s, 2, 16);
                s += __shfl_down_sync(0xffffffffu, s, 1, 16);
                if ((lane & 15) == 0) S->jn[fi >> 4] = s;
            }
            __syncthreads();

            float acc[4][4];
            #pragma unroll
            for (int r = 0; r < 4; r++)
                #pragma unroll
                for (int s = 0; s < 4; s++) acc[r][s] = 0.f;

            #pragma unroll
            for (int c = 0; c < 8; c++) {      // 8-dim chunks
                float4 qr[4][2];
                #pragma unroll
                for (int r = 0; r < 4; r++) {
                    qr[r][0] = *(const float4*)&S->xq[4 * w + r][c * 8];
                    qr[r][1] = *(const float4*)&S->xq[4 * w + r][c * 8 + 4];
                }
                #pragma unroll
                for (int s = 0; s < 4; s++) {
                    const int j = lane + 32 * s;
                    const float4 b0 = *(const float4*)&S->tile[j][c * 8];
                    const float4 b1 = *(const float4*)&S->tile[j][c * 8 + 4];
                    #pragma unroll
                    for (int r = 0; r < 4; r++) {
                        float a = acc[r][s];
                        a = fmaf(qr[r][0].x, b0.x, a);
                        a = fmaf(qr[r][0].y, b0.y, a);
                        a = fmaf(qr[r][0].z, b0.z, a);
                        a = fmaf(qr[r][0].w, b0.w, a);
                        a = fmaf(qr[r][1].x, b1.x, a);
                        a = fmaf(qr[r][1].y, b1.y, a);
                        a = fmaf(qr[r][1].z, b1.z, a);
                        a = fmaf(qr[r][1].w, b1.w, a);
                        acc[r][s] = a;
                    }
                }
            }
            // candidates ranked by jn - 2*dot (qn constant per row)
            #pragma unroll
            for (int s = 0; s < 4; s++) {
                const float nj = S->jn[lane + 32 * s];
                #pragma unroll
                for (int r = 0; r < 4; r++) {
                    float v = fmaf(acc[r][s], -2.f, nj);
                    if (v < m[r][5]) {
                        m[r][5] = v;
                        #pragma unroll
                        for (int i = 5; i > 0; i--)
                            if (m[r][i] < m[r][i - 1]) {
                                float tm = m[r][i]; m[r][i] = m[r][i - 1]; m[r][i - 1] = tm;
                            }
                    }
                }
            }
        }

        // per-row: extract top-6 over lanes, add qn, store
        #pragma unroll
        for (int r = 0; r < 4; r++) {
            float l0 = m[r][0], l1 = m[r][1], l2 = m[r][2];
            float l3 = m[r][3], l4 = m[r][4], l5 = m[r][5];
            float keep = 3.4e38f;
            #pragma unroll
            for (int i = 0; i < 6; i++) {
                float mv = l0;
                #pragma unroll
                for (int off = 16; off; off >>= 1)
                    mv = fminf(mv, __shfl_xor_sync(0xffffffffu, mv, off));
                if (lane == i) keep = mv;
                unsigned msk = __ballot_sync(0xffffffffu, l0 == mv);
                if (lane == (__ffs(msk) - 1)) {
                    l0 = l1; l1 = l2; l2 = l3; l3 = l4; l4 = l5; l5 = 3.4e38f;
                }
            }
            if (lane < 6)
                g_t6[g][q][4 * w + r][lane] = keep + S->qn[4 * w + r];
        }
        __syncthreads();
        if (tid == 0) {
            __threadfence();
            int old = atomicAdd(&g_qc[g], 1);
            S->merge = (old == NQ - 1);
        }
        __syncthreads();
        if (S->merge) {
            __threadfence();
            if (tid < 32) {
                int kk = *kp; if (kk > 5) kk = 5;
                float best[6];
                #pragma unroll
                for (int i = 0; i < 6; i++) best[i] = 3.4e38f;
                #pragma unroll
                for (int qq = 0; qq < NQ; qq++) {
                    #pragma unroll
                    for (int i = 0; i < 6; i++) {
                        float v = g_t6[g][qq][tid][i];
                        if (v < best[5]) {
                            best[5] = v;
                            #pragma unroll
                            for (int j2 = 5; j2 > 0; j2--)
                                if (best[j2] < best[j2 - 1]) {
                                    float tm = best[j2]; best[j2] = best[j2 - 1]; best[j2 - 1] = tm;
                                }
                        }
                    }
                }
                g_logrho[row0 + tid] = logf(fmaxf(best[kk], 1e-12f));
            }
            if (tid == 0) g_qc[g] = 0;   // reset for graph replay
        }
    } else {
        // ================= PREP (256 thr, 4 elems/thread) ================
        PrepS* P = (PrepS*)sm;
        const int col = bx - NBLK_KNN;
        float s1 = 0.f, s2 = 0.f;
        #pragma unroll
        for (int t = 0; t < 4; t++) {
            float v = act[(tid + 256 * t) * N_DIM + col];
            P->u[tid + 256 * t] = v;
            s1 += v;
            s2 += v * v;
        }
        P->red[tid] = s1; __syncthreads();
        for (int st = 128; st > 0; st >>= 1) {
            if (tid < st) P->red[tid] += P->red[tid + st];
            __syncthreads();
        }
        float tot1 = P->red[0]; __syncthreads();
        P->red[tid] = s2; __syncthreads();
        for (int st = 128; st > 0; st >>= 1) {
            if (tid < st) P->red[tid] += P->red[tid + st];
            __syncthreads();
        }
        if (tid == 0) {
            const float Bf = (float)B_ROWS;
            float mean = tot1 / Bf;
            float var  = (P->red[0] - Bf * mean * mean) / (Bf - 1.0f);
            float stdv = sqrtf(fmaxf(var, 0.f));
            float h    = fmaxf(1.06f * stdv * 0.25f, 1e-4f);
            float ih   = 1.0f / h;
            g_invh[col] = ih;
            P->scale    = ih;
        }
        __syncthreads();
        const float sc = P->scale;
        #pragma unroll
        for (int t = 0; t < 4; t++)
            P->u[tid + 256 * t] *= sc;

        for (int kk2 = 2; kk2 <= B_ROWS; kk2 <<= 1) {
            for (int jj = kk2 >> 1; jj > 0; jj >>= 1) {
                __syncthreads();
                #pragma unroll
                for (int t = 0; t < 4; t++) {
                    int i = tid + 256 * t;
                    int ixj = i ^ jj;
                    if (ixj > i) {
                        bool up = ((i & kk2) == 0);
                        float a = P->u[i], b = P->u[ixj];
                        if ((a > b) == up) { P->u[i] = b; P->u[ixj] = a; }
                    }
                }
            }
        }
        __syncthreads();
        #pragma unroll
        for (int t = 0; t < 4; t++)
            g_cols[col * B_ROWS + tid + 256 * t] = P->u[tid + 256 * t];
    }
}

// ---------------------------------------------------------------------------
// Kernel 2: KDE, one warp per 32-query chunk (Hermite moments + own Horner).
// grid = 256 (col*4 + quarter), block = 256 (8 warps = 8 chunks).
// ---------------------------------------------------------------------------
__global__ __launch_bounds__(256)
void k2(const int* __restrict__ kp, float* __restrict__ out) {
    __shared__ __align__(16) float u[B_ROWS];
    __shared__ int   bnd[8][4];
    __shared__ double dred[256];
    __shared__ int   sdone;

    const int tid  = threadIdx.x;
    const int lane = tid & 31;
    const int w    = tid >> 5;
    const int col  = blockIdx.x >> 2;
    const int q    = blockIdx.x & 3;
    const int c_lo = q * 4 + (w & 3);
    const int chunk = (w < 4) ? c_lo : (31 - c_lo);

    ((float4*)u)[tid] = ((const float4*)(g_cols + col * B_ROWS))[tid];
    __syncthreads();

    const float ih = g_invh[col];
    const float c2 = 2.0f * ih;
    const int   q0 = chunk * 32;
    const float x  = u[q0 + lane];
    const float cen = 0.5f * (u[q0] + u[q0 + 31]);

    if (tid < 32) {
        int wi = tid >> 2, i2 = tid & 3;
        int cl = q * 4 + (wi & 3);
        int ch = (wi < 4) ? cl : (31 - cl);
        float xmn = u[ch * 32], xmx = u[ch * 32 + 31];
        float tgt = (i2 == 0) ? xmn - TS : (i2 == 1) ? xmx + TS
                  : (i2 == 2) ? TS - xmn : c2 - TS - xmx;
        int pos = 0;
        #pragma unroll
        for (int step = 1024; step; step >>= 1) {
            int np = pos + step;
            if (np <= B_ROWS && u[np - 1] < tgt) pos = np;
        }
        bnd[wi][i2] = pos;
    }
    __syncthreads();
    const int a0 = bnd[w][0], b0 = bnd[w][1];
    const int bL = bnd[w][2], aR = bnd[w][3];

    // ---- Hermite moments: lane-strided over this warp's window ----
    float M[NMOM];
    #pragma unroll
    for (int n = 0; n < NMOM; n++) M[n] = 0.f;
    {
        constexpr float INV[NMOM] = {0.f, 1.f, 0.5f, 0.33333334f, 0.25f, 0.2f,
            0.16666667f, 0.14285715f, 0.125f, 0.11111111f, 0.1f, 0.09090909f,
            0.08333334f};
        for (int j = a0 + lane; j < b0; j += 32) {
            float uj = u[j] - cen;
            float wg = ex2(K2C * uj * uj);
            float bp = wg, bc = wg * uj;
            M[0] += bp;
            M[1] += bc;
            #pragma unroll
            for (int n = 1; n < NMOM - 1; n++) {
                float bn = fmaf(uj, bc, -bp) * INV[n + 1];
                M[n + 1] += bn;
                bp = bc; bc = bn;
            }
        }
    }
    // butterfly: every lane ends with the full sums
    #pragma unroll
    for (int n = 0; n < NMOM; n++) {
        #pragma unroll
        for (int off = 16; off; off >>= 1)
            M[n] += __shfl_xor_sync(0xffffffffu, M[n], off);
    }

    // ---- per-lane Horner ----
    const float delta = x - cen;
    float f = M[NMOM - 1];
    #pragma unroll
    for (int n = NMOM - 2; n >= 0; n--)
        f = fmaf(f, delta, M[n]);

    // ---- reflections: per-lane full-range (broadcast LDS) ----
    for (int j = 0; j < bL; j++) {
        float s = x + u[j];
        f += ex2(K2C * s * s);
    }
    {
        const float xc = x - c2;
        for (int j = aR; j < B_ROWS; j++) {
            float s = xc + u[j];
            f += ex2(K2C * s * s);
        }
    }

    const float Bf = (float)B_ROWS;
    const float scale = ih * (1.0f / (Bf * 2.5066282746310002f));
    float l = logf(f * scale + 1e-8f);
    #pragma unroll
    for (int off = 16; off; off >>= 1)
        l += __shfl_xor_sync(0xffffffffu, l, off);
    if (lane == 0)
        g_partials[col * QCH + chunk] = l;

    // ---- completion counter + final assembly ----
    __syncthreads();
    if (tid == 0) {
        __threadfence();
        unsigned p = atomicAdd(&g_done, 1);
        sdone = (p == NBLK_K2 - 1);
    }
    __syncthreads();
    if (!sdone) return;
    __threadfence();

    if (tid < N_DIM) {
        float t = 0.f;
        #pragma unroll
        for (int c = 0; c < QCH; c++)
            t += g_partials[tid * QCH + c];
        out[1 + tid] = -t / (float)B_ROWS;
    }
    {
        double s = 0.0;
        for (int i = tid; i < B_ROWS; i += 256) s += (double)g_logrho[i];
        dred[tid] = s; __syncthreads();
        for (int st = 128; st > 0; st >>= 1) {
            if (tid < st) dred[tid] += dred[tid + st];
            __syncthreads();
        }
        if (tid == 0) {
            const int k = *kp;
            const double EULER    = 0.5772156649015328606;
            const double DG_B     = 6.9309834448765934;     // psi(1024)
            const double LGAMMA33 = 81.55795945611503558;   // lgamma(64/2+1)
            const double LOG_PI   = 1.1447298858494001741;
            const double INV_LN2  = 1.4426950408889634074;
            double dg_k = -EULER;
            for (int i = 1; i < k; i++) dg_k += 1.0 / (double)i;
            double log_c_d = 0.5 * (double)N_DIM * LOG_PI - LGAMMA33;
            double mean_lr = dred[0] / (double)B_ROWS;
            double h_nats = -dg_k + DG_B + log_c_d + (double)N_DIM * 0.5 * mean_lr;
            out[0] = (float)(h_nats * INV_LN2);
        }
    }
}

// ---------------------------------------------------------------------------
extern "C" void kernel_launch(void* const* d_in, const int* in_sizes, int n_in,
                              void* d_out, int out_size) {
    const float* act = (const float*)d_in[0];
    const int*   kp  = (const int*)d_in[1];
    float* out = (float*)d_out;
    (void)in_sizes; (void)n_in; (void)out_size;

    k1<<<NBLK_KNN + N_DIM, 256>>>(act, kp);
    k2<<<NBLK_K2, 256>>>(kp, out);
}